// round 17
// baseline (speedup 1.0000x reference)
#include <cuda_runtime.h>
#include <math.h>

// B=2, S=2048, D=1024, H=16, HD=64. Scratch row-major [b*S+s][h*64+e].
__device__ float n_q[4096*1024];
__device__ float n_k[4096*1024];
__device__ float n_v[4096*1024];
__device__ float n_ctx[4096*1024];

// ---------------------------------------------------------------------------
// Split helpers.
// ---------------------------------------------------------------------------
__device__ __forceinline__ void cvt_hl(float v, float& h, float& l) {
    unsigned u;
    asm("cvt.rna.tf32.f32 %0, %1;" : "=r"(u) : "f"(v));
    h = __uint_as_float(u);
    l = v - h;
}

__device__ __forceinline__ void mma8(float* d, const unsigned* a, unsigned b0, unsigned b1) {
    asm volatile(
        "mma.sync.aligned.m16n8k8.row.col.f32.tf32.tf32.f32 "
        "{%0,%1,%2,%3}, {%4,%5,%6,%7}, {%8,%9}, {%0,%1,%2,%3};"
        : "+f"(d[0]), "+f"(d[1]), "+f"(d[2]), "+f"(d[3])
        : "r"(a[0]), "r"(a[1]), "r"(a[2]), "r"(a[3]), "r"(b0), "r"(b1));
}

// bf16 k16 mma
__device__ __forceinline__ void mma16(float* d, const unsigned* a, unsigned b0, unsigned b1) {
    asm volatile(
        "mma.sync.aligned.m16n8k16.row.col.f32.bf16.bf16.f32 "
        "{%0,%1,%2,%3}, {%4,%5,%6,%7}, {%8,%9}, {%0,%1,%2,%3};"
        : "+f"(d[0]), "+f"(d[1]), "+f"(d[2]), "+f"(d[3])
        : "r"(a[0]), "r"(a[1]), "r"(a[2]), "r"(a[3]), "r"(b0), "r"(b1));
}

__device__ __forceinline__ unsigned short f2bf(float v) {
    unsigned u = __float_as_uint(v);
    u = (u + 0x7FFFu + ((u >> 16) & 1u)) >> 16;
    return (unsigned short)u;
}
__device__ __forceinline__ float bf2f(unsigned short b) {
    return __uint_as_float(((unsigned)b) << 16);
}
// Pack (v0 = even k, v1 = odd k) into hi-word / lo-word bf16x2.
__device__ __forceinline__ void pack_hl(float v0, float v1, unsigned& wh, unsigned& wl) {
    const unsigned short h0 = f2bf(v0);
    const unsigned short h1 = f2bf(v1);
    const unsigned short l0 = f2bf(v0 - bf2f(h0));
    const unsigned short l1 = f2bf(v1 - bf2f(h1));
    wh = (unsigned)h0 | ((unsigned)h1 << 16);
    wl = (unsigned)l0 | ((unsigned)l1 << 16);
}

// ---------------------------------------------------------------------------
// TF32 GEMM — VERBATIM from passing R13/R15/R16. C = A @ W^T.
// ---------------------------------------------------------------------------
#define LDP 132

__global__ void __launch_bounds__(256) gemm_tf32(
    const float* __restrict__ A,
    const float* __restrict__ W0, const float* __restrict__ W1, const float* __restrict__ W2,
    float* __restrict__ C0, float* __restrict__ C1, float* __restrict__ C2)
{
    const float* W = (blockIdx.z == 0) ? W0 : (blockIdx.z == 1) ? W1 : W2;
    float*       C = (blockIdx.z == 0) ? C0 : (blockIdx.z == 1) ? C1 : C2;

    __shared__ float As[16 * LDP];
    __shared__ float Bs[16 * LDP];

    const int t    = threadIdx.x;
    const int lane = t & 31;
    const int wid  = t >> 5;
    const int wm   = (wid & 3) << 5;
    const int wn   = (wid >> 2) << 6;
    const int m0   = blockIdx.y << 7;
    const int n0   = blockIdx.x << 7;

    const int row0 = t >> 2;
    const int kg   = (t & 3) << 2;

    const int lq = lane >> 2;
    const int lr = lane & 3;

    float acc[2][8][4];
#pragma unroll
    for (int mt = 0; mt < 2; mt++)
#pragma unroll
        for (int nt = 0; nt < 8; nt++)
#pragma unroll
            for (int f = 0; f < 4; f++) acc[mt][nt][f] = 0.f;

    for (int k0 = 0; k0 < 1024; k0 += 16) {
        float4 a0v = *(const float4*)(A + (m0 + row0)      * 1024 + k0 + kg);
        float4 a1v = *(const float4*)(A + (m0 + row0 + 64) * 1024 + k0 + kg);
        float4 b0v = *(const float4*)(W + (n0 + row0)      * 1024 + k0 + kg);
        float4 b1v = *(const float4*)(W + (n0 + row0 + 64) * 1024 + k0 + kg);

        __syncthreads();

        As[(kg+0)*LDP + row0] = a0v.x;
        As[(kg+1)*LDP + row0] = a0v.y;
        As[(kg+2)*LDP + row0] = a0v.z;
        As[(kg+3)*LDP + row0] = a0v.w;
        As[(kg+0)*LDP + row0 + 64] = a1v.x;
        As[(kg+1)*LDP + row0 + 64] = a1v.y;
        As[(kg+2)*LDP + row0 + 64] = a1v.z;
        As[(kg+3)*LDP + row0 + 64] = a1v.w;
        Bs[(kg+0)*LDP + row0] = b0v.x;
        Bs[(kg+1)*LDP + row0] = b0v.y;
        Bs[(kg+2)*LDP + row0] = b0v.z;
        Bs[(kg+3)*LDP + row0] = b0v.w;
        Bs[(kg+0)*LDP + row0 + 64] = b1v.x;
        Bs[(kg+1)*LDP + row0 + 64] = b1v.y;
        Bs[(kg+2)*LDP + row0 + 64] = b1v.z;
        Bs[(kg+3)*LDP + row0 + 64] = b1v.w;

        __syncthreads();

#pragma unroll
        for (int ks = 0; ks < 2; ks++) {
            const int kk = (ks << 3) + lr;

            unsigned ah[2][4], al[2][4];
#pragma unroll
            for (int mt = 0; mt < 2; mt++) {
                const int r = wm + (mt << 4) + lq;
                float h, l;
                cvt_hl(As[kk*LDP + r],         h, l); ah[mt][0]=__float_as_uint(h); al[mt][0]=__float_as_uint(l);
                cvt_hl(As[kk*LDP + r + 8],     h, l); ah[mt][1]=__float_as_uint(h); al[mt][1]=__float_as_uint(l);
                cvt_hl(As[(kk+4)*LDP + r],     h, l); ah[mt][2]=__float_as_uint(h); al[mt][2]=__float_as_uint(l);
                cvt_hl(As[(kk+4)*LDP + r + 8], h, l); ah[mt][3]=__float_as_uint(h); al[mt][3]=__float_as_uint(l);
            }

#pragma unroll
            for (int nt = 0; nt < 8; nt++) {
                const int c = wn + (nt << 3) + lq;
                float bh0, bl0, bh1, bl1;
                cvt_hl(Bs[kk*LDP + c],     bh0, bl0);
                cvt_hl(Bs[(kk+4)*LDP + c], bh1, bl1);
                const unsigned ubh0 = __float_as_uint(bh0), ubh1 = __float_as_uint(bh1);
                const unsigned ubl0 = __float_as_uint(bl0), ubl1 = __float_as_uint(bl1);
#pragma unroll
                for (int mt = 0; mt < 2; mt++) {
                    mma8(acc[mt][nt], ah[mt], ubh0, ubh1);
                    mma8(acc[mt][nt], ah[mt], ubl0, ubl1);
                    mma8(acc[mt][nt], al[mt], ubh0, ubh1);
                }
            }
        }
    }

#pragma unroll
    for (int mt = 0; mt < 2; mt++)
#pragma unroll
        for (int nt = 0; nt < 8; nt++) {
            const int m = m0 + wm + (mt << 4) + lq;
            const int n = n0 + wn + (nt << 3) + (lr << 1);
            *(float2*)&C[m * 1024 + n]       = make_float2(acc[mt][nt][0], acc[mt][nt][1]);
            *(float2*)&C[(m + 8) * 1024 + n] = make_float2(acc[mt][nt][2], acc[mt][nt][3]);
        }
}

// ---------------------------------------------------------------------------
// RoPE — VERBATIM from passing R8-R13 (powf/cosf/sinf). In-place on n_q/n_k.
// ---------------------------------------------------------------------------
__global__ void nrope(float* q, float* k)
{
    const int g = blockIdx.x * 256 + threadIdx.x;
    const int i = g & 31;
    const int h = (g >> 5) & 15;
    const int m = g >> 9;
    const int s = m & 2047;
    const float freq = powf(10000.0f, -(float)i / 32.0f);
    const float ang  = (float)s * freq;
    const float c = cosf(ang), sn = sinf(ang);
    const int o = m * 1024 + h * 64 + i;
    float x1 = q[o], x2 = q[o + 32];
    q[o]      = x1 * c - x2 * sn;
    q[o + 32] = x2 * c + x1 * sn;
    x1 = k[o]; x2 = k[o + 32];
    k[o]      = x1 * c - x2 * sn;
    k[o + 32] = x2 * c + x1 * sn;
}

// ---------------------------------------------------------------------------
// Flash attention v4: 3-pass split-bf16 m16n8k16.
// All operands split/packed ONCE at staging; no at-use conversion.
// Q,K natural row-major (A row / B col layouts) -> no global transpose.
// V staged transposed [e][keypair] via u16 stores.
// S fp32 stride 67 (conflict-free row reads). Softmax structure = R15.
// Smem 91.6 KB -> 2 CTAs/SM.
// ---------------------------------------------------------------------------
#define LS 67          // S stride (floats)
#define LPW 35         // packed-array stride (uint32 words per row of 32 pairs)
#define ATT_WORDS (4288 + 8*2240 + 704)
#define ATT_SMEM  (ATT_WORDS * 4)

__global__ void __launch_bounds__(256, 2) attn_bf16()
{
    extern __shared__ float smf[];
    float*    S  = smf;                         // [64][LS]
    unsigned* Qh = (unsigned*)(smf + 4288);
    unsigned* Ql = Qh + 2240;
    unsigned* Kh = Ql + 2240;
    unsigned* Kl = Kh + 2240;
    unsigned* Vh = Kl + 2240;
    unsigned* Vl = Vh + 2240;
    unsigned* Ph = Vl + 2240;
    unsigned* Pl = Ph + 2240;
    float*    mS = (float*)(Pl + 2240);         // [64]
    float*    cS = mS + 64;
    float*    lS = cS + 64;
    float*    Mx = lS + 64;                     // [4][64]
    float*    Sm = Mx + 256;                    // [4][64]

    const int t    = threadIdx.x;
    const int lane = t & 31, wid = t >> 5;
    const int lq   = lane >> 2, lr = lane & 3;
    const int wm   = (wid & 3) << 4;     // q base
    const int wn   = (wid >> 2) << 5;    // key/e base: 0 or 32
    const int qt   = blockIdx.x;         // 0..31
    const int bh   = blockIdx.y;
    const int b    = bh >> 4, h = bh & 15;

    const float* qp = n_q + (size_t)(b*2048 + (qt << 6))*1024 + (h << 6);
    const float* kp = n_k + (size_t)(b*2048)*1024 + (h << 6);
    const float* vp = n_v + (size_t)(b*2048)*1024 + (h << 6);

    // Stage Q once: scale 1/8, split+pack. [q-row][d-pair]
#pragma unroll
    for (int p = 0; p < 4; p++) {
        const int idx = (p << 8) + t;
        const int r = idx >> 4, d4 = (idx & 15) << 2;
        float4 v = *(const float4*)(qp + (size_t)r*1024 + d4);
        v.x *= 0.125f; v.y *= 0.125f; v.z *= 0.125f; v.w *= 0.125f;
        unsigned wh0, wl0, wh1, wl1;
        pack_hl(v.x, v.y, wh0, wl0);
        pack_hl(v.z, v.w, wh1, wl1);
        const int base = r*LPW + (d4 >> 1);
        Qh[base] = wh0; Qh[base+1] = wh1;
        Ql[base] = wl0; Ql[base+1] = wl1;
    }
    if (t < 64) { mS[t] = -1e30f; lS[t] = 0.f; }

    float acc[4][4];
#pragma unroll
    for (int nt = 0; nt < 4; nt++)
#pragma unroll
        for (int f = 0; f < 4; f++) acc[nt][f] = 0.f;

    const int row = t & 63, ck = t >> 6;

    for (int kt = 0; kt < 32; kt++) {
        __syncthreads();   // A: prev PV done reading Vh/Vl/Ph/Pl; Q ready iter 0

        // Stage K [key][d-pair] packed
#pragma unroll
        for (int p = 0; p < 4; p++) {
            const int idx = (p << 8) + t;
            const int r = idx >> 4, d4 = (idx & 15) << 2;
            const float4 v = *(const float4*)(kp + (size_t)((kt << 6) + r)*1024 + d4);
            unsigned wh0, wl0, wh1, wl1;
            pack_hl(v.x, v.y, wh0, wl0);
            pack_hl(v.z, v.w, wh1, wl1);
            const int base = r*LPW + (d4 >> 1);
            Kh[base] = wh0; Kh[base+1] = wh1;
            Kl[base] = wl0; Kl[base+1] = wl1;
        }
        // Stage V transposed [e][key-pair] via u16 halves
#pragma unroll
        for (int p = 0; p < 4; p++) {
            const int idx = (p << 8) + t;
            const int key = idx >> 4, e4 = (idx & 15) << 2;
            const float4 v = *(const float4*)(vp + (size_t)((kt << 6) + key)*1024 + e4);
            const float* pv = (const float*)&v;
#pragma unroll
            for (int u = 0; u < 4; u++) {
                const int e = e4 + u;
                const float val = pv[u];
                const unsigned short hh = f2bf(val);
                const unsigned short ll = f2bf(val - bf2f(hh));
                const int hw = (e*LPW + (key >> 1))*2 + (key & 1);
                ((unsigned short*)Vh)[hw] = hh;
                ((unsigned short*)Vl)[hw] = ll;
            }
        }
        __syncthreads();   // B: tiles staged

        // ---- QK: S[64q x 64key], warp 16q x 32key, 3-pass bf16 ----
        float sacc[4][4];
#pragma unroll
        for (int nt = 0; nt < 4; nt++)
#pragma unroll
            for (int f = 0; f < 4; f++) sacc[nt][f] = 0.f;

#pragma unroll
        for (int s4 = 0; s4 < 4; s4++) {
            const int koff = (s4 << 3) + lr;
            const int ra = (wm + lq)*LPW, rb = (wm + lq + 8)*LPW;
            const unsigned ah[4] = {Qh[ra+koff], Qh[rb+koff], Qh[ra+koff+4], Qh[rb+koff+4]};
            const unsigned al[4] = {Ql[ra+koff], Ql[rb+koff], Ql[ra+koff+4], Ql[rb+koff+4]};
#pragma unroll
            for (int nt = 0; nt < 4; nt++) {
                const int c = (wn + (nt << 3) + lq)*LPW;
                const unsigned bh0 = Kh[c+koff], bh1 = Kh[c+koff+4];
                const unsigned bl0 = Kl[c+koff], bl1 = Kl[c+koff+4];
                mma16(sacc[nt], ah, bh0, bh1);
                mma16(sacc[nt], ah, bl0, bl1);
                mma16(sacc[nt], al, bh0, bh1);
            }
        }

        // Store S row-major [q][key]
#pragma unroll
        for (int nt = 0; nt < 4; nt++) {
            const int cb = wn + (nt << 3) + (lr << 1);
            const int r  = wm + lq;
            S[r*LS + cb]       = sacc[nt][0];
            S[r*LS + cb + 1]   = sacc[nt][1];
            S[(r+8)*LS + cb]   = sacc[nt][2];
            S[(r+8)*LS + cb+1] = sacc[nt][3];
        }
        __syncthreads();   // C: S complete

        // ---- Softmax distributed: thread = (row, 16-key chunk ck) ----
        float lm = -1e30f;
#pragma unroll
        for (int u = 0; u < 16; u++)
            lm = fmaxf(lm, S[row*LS + (ck << 4) + u]);
        Mx[(ck << 6) + row] = lm;
        __syncthreads();   // D
        if (t < 64) {
            const float mo = mS[t];
            float mn = fmaxf(fmaxf(Mx[t], Mx[64+t]), fmaxf(Mx[128+t], Mx[192+t]));
            mn = fmaxf(mo, mn);
            mS[t] = mn;
            cS[t] = __expf(mo - mn);
        }
        __syncthreads();   // E
        {
            const float mn = mS[row];
            float lsum = 0.f;
#pragma unroll
            for (int i = 0; i < 8; i++) {
                const int k0 = (ck << 4) + (i << 1);
                const float p0 = __expf(S[row*LS + k0]     - mn);
                const float p1 = __expf(S[row*LS + k0 + 1] - mn);
                lsum += p0 + p1;
                unsigned wh, wl;
                pack_hl(p0, p1, wh, wl);
                Ph[row*LPW + (k0 >> 1)] = wh;
                Pl[row*LPW + (k0 >> 1)] = wl;
            }
            Sm[(ck << 6) + row] = lsum;
        }
        __syncthreads();   // F: P + partial sums ready
        if (t < 64)
            lS[t] = lS[t]*cS[t] + Sm[t] + Sm[64+t] + Sm[128+t] + Sm[192+t];

        // ---- PV: O += P @ V, warp 16q x 32e, 3-pass bf16 ----
        {
            const float c0 = cS[wm + lq], c1 = cS[wm + lq + 8];
#pragma unroll
            for (int nt = 0; nt < 4; nt++) {
                acc[nt][0] *= c0; acc[nt][1] *= c0;
                acc[nt][2] *= c1; acc[nt][3] *= c1;
            }
#pragma unroll
            for (int s4 = 0; s4 < 4; s4++) {
                const int koff = (s4 << 3) + lr;
                const int ra = (wm + lq)*LPW, rb = (wm + lq + 8)*LPW;
                const unsigned ah[4] = {Ph[ra+koff], Ph[rb+koff], Ph[ra+koff+4], Ph[rb+koff+4]};
                const unsigned al[4] = {Pl[ra+koff], Pl[rb+koff], Pl[ra+koff+4], Pl[rb+koff+4]};
#pragma unroll
                for (int nt = 0; nt < 4; nt++) {
                    const int e = (wn + (nt << 3) + lq)*LPW;
                    const unsigned bh0 = Vh[e+koff], bh1 = Vh[e+koff+4];
                    const unsigned bl0 = Vl[e+koff], bl1 = Vl[e+koff+4];
                    mma16(acc[nt], ah, bh0, bh1);
                    mma16(acc[nt], ah, bl0, bl1);
                    mma16(acc[nt], al, bh0, bh1);
                }
            }
        }
    }

    __syncthreads();
    if (t < 64) cS[t] = 1.f / lS[t];
    __syncthreads();

    const float i0 = cS[wm + lq], i1 = cS[wm + lq + 8];
#pragma unroll
    for (int nt = 0; nt < 4; nt++) {
        const int q0 = (qt << 6) + wm + lq;
        const int e  = wn + (nt << 3) + (lr << 1);
        const size_t base = (size_t)(b*2048 + q0)*1024 + (h << 6) + e;
        *(float2*)&n_ctx[base]           = make_float2(acc[nt][0]*i0, acc[nt][1]*i0);
        *(float2*)&n_ctx[base + 8*1024]  = make_float2(acc[nt][2]*i1, acc[nt][3]*i1);
    }
}

// ---------------------------------------------------------------------------
extern "C" void kernel_launch(void* const* d_in, const int* in_sizes, int n_in,
                              void* d_out, int out_size)
{
    const float* x  = (const float*)d_in[0];
    const float* Wq = (const float*)d_in[1];
    const float* Wk = (const float*)d_in[2];
    const float* Wv = (const float*)d_in[3];
    const float* Wo = (const float*)d_in[4];
    float* out = (float*)d_out;

    float* gq;  cudaGetSymbolAddress((void**)&gq, n_q);
    float* gk;  cudaGetSymbolAddress((void**)&gk, n_k);
    float* gv;  cudaGetSymbolAddress((void**)&gv, n_v);
    float* gc;  cudaGetSymbolAddress((void**)&gc, n_ctx);

    cudaFuncSetAttribute(attn_bf16, cudaFuncAttributeMaxDynamicSharedMemorySize, ATT_SMEM);

    gemm_tf32<<<dim3(8, 32, 3), 256>>>(x, Wq, Wk, Wv, gq, gk, gv);
    nrope<<<4096 * 16 * 32 / 256, 256>>>(gq, gk);
    attn_bf16<<<dim3(32, 32), 256, ATT_SMEM>>>();
    gemm_tf32<<<dim3(8, 32, 1), 256>>>(gc, Wo, Wo, Wo, out, out, out);
}